// round 17
// baseline (speedup 1.0000x reference)
#include <cuda_runtime.h>
#include <cuda_bf16.h>
#include <cstdint>

// FM-CTR kernel — R12/R14: TMA bulk gathers (cp.async.bulk) to bypass the
// L1tex/LSU outstanding-miss cap that pins the LDG path at ~60% DRAM.
// Inputs (metadata order):
//  d_in[0]: dense_x     f32 [16384, 13]
//  d_in[1]: discrete_x  i32 [16384, 26]
//  d_in[2]: emb_tables  f32 [26, 50000, 128]
//  d_in[3]: dense_w     f32 [128, 13]
//  d_in[4]: dense_b     f32 [128]
// Output: f32 [16384]
//
// 1 warp per row. Lane 0 issues 26 x 512B cp.async.bulk copies (one full
// embedding row each) into this warp's smem buffer, tracked by one mbarrier
// with expect_tx = 26*512. Dense matvec runs under the TMA shadow. After an
// acquire-wait, lane l consumes its float4 slice of each staged row (LDS.128,
// conflict-free). Requests ride the TMA engine's queues, not LSU MSHRs.

#define N_TABLES 26
#define VOCAB    50000
#define EMBED_DIM 128
#define DENSE_DIM 13
#define BATCH    16384
#define WARPS_PER_BLOCK 8
#define THREADS (WARPS_PER_BLOCK * 32)
#define ROW_BYTES (EMBED_DIM * 4)                       // 512
#define BUF_PER_WARP (N_TABLES * ROW_BYTES)             // 13312
#define SMEM_BUF_BASE 128                               // mbarriers live below
#define SMEM_BYTES (SMEM_BUF_BASE + WARPS_PER_BLOCK * BUF_PER_WARP)  // 106624

__global__ __launch_bounds__(THREADS) void fm_ctr_kernel(
    const float* __restrict__ dense_x,
    const int*   __restrict__ discrete_x,
    const float* __restrict__ emb,
    const float* __restrict__ dense_w,
    const float* __restrict__ dense_b,
    float* __restrict__ out)
{
    extern __shared__ __align__(16) char smem[];

    const int warp_in_blk = threadIdx.x >> 5;
    const int lane  = threadIdx.x & 31;
    const int gwarp = blockIdx.x * WARPS_PER_BLOCK + warp_in_blk;
    if (gwarp >= BATCH) return;

    // smem addresses (u32, shared window)
    unsigned smem_base = (unsigned)__cvta_generic_to_shared(smem);
    unsigned mbar  = smem_base + warp_in_blk * 8;
    unsigned mybuf = smem_base + SMEM_BUF_BASE + warp_in_blk * BUF_PER_WARP;

    // Per-warp mbarrier init (only this warp ever touches it; phase 0 only).
    if (lane == 0) {
        asm volatile("mbarrier.init.shared.b64 [%0], %1;"
                     :: "r"(mbar), "r"(1) : "memory");
    }
    __syncwarp();

    // Indices: lanes 0..25 load, broadcast via shfl; lane 0 issues the copies.
    int my_idx = 0;
    if (lane < N_TABLES)
        my_idx = discrete_x[gwarp * N_TABLES + lane];

    if (lane == 0) {
        asm volatile("mbarrier.arrive.expect_tx.shared.b64 _, [%0], %1;"
                     :: "r"(mbar), "r"(BUF_PER_WARP) : "memory");
    }
    #pragma unroll
    for (int t = 0; t < N_TABLES; t++) {
        int id = __shfl_sync(0xffffffffu, my_idx, t);
        if (lane == 0) {
            const float* src = emb + (unsigned)(t * VOCAB * EMBED_DIM)
                                   + ((unsigned)id << 7);
            asm volatile(
                "cp.async.bulk.shared::cluster.global.mbarrier::complete_tx::bytes "
                "[%0], [%1], %2, [%3];"
                :: "r"(mybuf + t * ROW_BYTES), "l"(src), "r"(ROW_BYTES), "r"(mbar)
                : "memory");
        }
    }

    // ---- Dense matvec under the TMA shadow ----
    float4 s, q;
    {
        float xr[DENSE_DIM];
        #pragma unroll
        for (int k = 0; k < DENSE_DIM; k++)
            xr[k] = __ldg(dense_x + gwarp * DENSE_DIM + k);

        float e0 = __ldg(dense_b + 4 * lane + 0);
        float e1 = __ldg(dense_b + 4 * lane + 1);
        float e2 = __ldg(dense_b + 4 * lane + 2);
        float e3 = __ldg(dense_b + 4 * lane + 3);
        #pragma unroll
        for (int k = 0; k < DENSE_DIM; k++) {
            e0 = fmaf(xr[k], __ldg(dense_w + (4 * lane + 0) * DENSE_DIM + k), e0);
            e1 = fmaf(xr[k], __ldg(dense_w + (4 * lane + 1) * DENSE_DIM + k), e1);
            e2 = fmaf(xr[k], __ldg(dense_w + (4 * lane + 2) * DENSE_DIM + k), e2);
            e3 = fmaf(xr[k], __ldg(dense_w + (4 * lane + 3) * DENSE_DIM + k), e3);
        }
        s = make_float4(e0, e1, e2, e3);
        q = make_float4(e0 * e0, e1 * e1, e2 * e2, e3 * e3);
    }

    // ---- Acquire-wait on the mbarrier (phase 0), all lanes ----
    {
        unsigned done;
        asm volatile(
            "{\n\t.reg .pred p;\n\t"
            "mbarrier.try_wait.parity.acquire.cta.shared::cta.b64 p, [%1], %2;\n\t"
            "selp.b32 %0, 1, 0, p;\n\t}"
            : "=r"(done) : "r"(mbar), "r"(0) : "memory");
        if (!done) {
            asm volatile(
                "{\n\t.reg .pred P1;\n\t"
                "W_%=:\n\t"
                "mbarrier.try_wait.parity.acquire.cta.shared::cta.b64 P1, [%0], %1, 0x989680;\n\t"
                "@P1 bra.uni D_%=;\n\t"
                "bra.uni W_%=;\n\t"
                "D_%=:\n\t}"
                :: "r"(mbar), "r"(0) : "memory");
        }
    }

    // ---- Consume staged rows: lane l reads its 16B of each table row ----
    #pragma unroll
    for (int t = 0; t < N_TABLES; t++) {
        float4 v;
        asm volatile("ld.shared.v4.f32 {%0,%1,%2,%3}, [%4];"
                     : "=f"(v.x), "=f"(v.y), "=f"(v.z), "=f"(v.w)
                     : "r"(mybuf + t * ROW_BYTES + lane * 16));
        s.x += v.x; s.y += v.y; s.z += v.z; s.w += v.w;
        q.x = fmaf(v.x, v.x, q.x);
        q.y = fmaf(v.y, v.y, q.y);
        q.z = fmaf(v.z, v.z, q.z);
        q.w = fmaf(v.w, v.w, q.w);
    }

    // FM partial for my 4 dims: 0.5 * (S^2 - sumsq)
    float fm = 0.5f * ((s.x * s.x - q.x) + (s.y * s.y - q.y) +
                       (s.z * s.z - q.z) + (s.w * s.w - q.w));

    #pragma unroll
    for (int o = 16; o > 0; o >>= 1)
        fm += __shfl_down_sync(0xffffffffu, fm, o);

    if (lane == 0) out[gwarp] = fm;
}

extern "C" void kernel_launch(void* const* d_in, const int* in_sizes, int n_in,
                              void* d_out, int out_size)
{
    const float* dense_x    = (const float*)d_in[0];
    const int*   discrete_x = (const int*)d_in[1];
    const float* emb        = (const float*)d_in[2];
    const float* dense_w    = (const float*)d_in[3];
    const float* dense_b    = (const float*)d_in[4];
    float* out = (float*)d_out;

    // Unconditional (deterministic) attribute set; host-side, not a stream op.
    cudaFuncSetAttribute(fm_ctr_kernel,
                         cudaFuncAttributeMaxDynamicSharedMemorySize,
                         SMEM_BYTES);

    const int blocks = (BATCH + WARPS_PER_BLOCK - 1) / WARPS_PER_BLOCK;
    fm_ctr_kernel<<<blocks, THREADS, SMEM_BYTES>>>(dense_x, discrete_x, emb,
                                                   dense_w, dense_b, out);
}